// round 15
// baseline (speedup 1.0000x reference)
#include <cuda_runtime.h>
#include <cuda_fp16.h>
#include <cstdint>

#define BATCH 8
#define NDIM  16384
#define CDIM  512
#define KSPLIT 8
#define KSEG  (NDIM / KSPLIT)   // 2048
#define KBLK  (KSEG / 16)       // 128 4KB-blocks per K segment

// Tiled-swizzled operand storage: one 4096B block per (128-tile, K=16 stage).
// Block = 128 rows x 16 halves; unit u = 2*r + h (16B), at ((u ^ ((u>>3)&1)) << 4).
__device__ __half g_XtT_h[(size_t)BATCH * 4 * 1024 * 2048];  // [b][ct][nstage]
__device__ __half g_XtT_l[(size_t)BATCH * 4 * 1024 * 2048];
__device__ __half g_XcT_h[(size_t)BATCH * 128 * 32 * 2048];  // [b][nt][cstage]
__device__ __half g_MT_h [(size_t)BATCH * 4 * 32 * 2048];    // [b][it][cstage]
__device__ float  g_Epart[(size_t)KSPLIT * BATCH * CDIM * CDIM];

// ---- helpers -------------------------------------------------------------
__device__ __forceinline__ uint32_t s2u(const void* p) {
    uint32_t a;
    asm("{ .reg .u64 t; cvta.to.shared.u64 t, %1; cvt.u32.u64 %0, t; }" : "=r"(a) : "l"(p));
    return a;
}
__device__ __forceinline__ void ldm4(uint32_t* r, uint32_t a) {
    asm volatile("ldmatrix.sync.aligned.m8n8.x4.shared.b16 {%0,%1,%2,%3},[%4];"
                 : "=r"(r[0]), "=r"(r[1]), "=r"(r[2]), "=r"(r[3]) : "r"(a));
}
__device__ __forceinline__ void mma16816(float* d, const uint32_t* a, const uint32_t* b) {
    asm volatile("mma.sync.aligned.m16n8k16.row.col.f32.f16.f16.f32 "
                 "{%0,%1,%2,%3},{%4,%5,%6,%7},{%8,%9},{%0,%1,%2,%3};"
                 : "+f"(d[0]), "+f"(d[1]), "+f"(d[2]), "+f"(d[3])
                 : "r"(a[0]), "r"(a[1]), "r"(a[2]), "r"(a[3]), "r"(b[0]), "r"(b[1]));
}
#define MBI(a, n) asm volatile("mbarrier.init.shared.b64 [%0], %1;" :: "r"(a), "r"((uint32_t)(n)) : "memory")
#define MBA(a)    asm volatile("mbarrier.arrive.shared.b64 _, [%0];" :: "r"(a) : "memory")
#define MBX(a, tx) asm volatile("mbarrier.arrive.expect_tx.shared.b64 _, [%0], %1;" :: "r"(a), "r"((uint32_t)(tx)) : "memory")
#define MBW(a, p) do { \
    asm volatile("{\n\t.reg .pred P;\n\tWL_%=:\n\t" \
        "mbarrier.try_wait.parity.acquire.cta.shared::cta.b64 P, [%0], %1, 0x989680;\n\t" \
        "@P bra.uni WD_%=;\n\tbra.uni WL_%=;\n\tWD_%=:\n\t}" \
        :: "r"(a), "r"((uint32_t)(p)) : "memory"); } while (0)
#define BULK(dst, src, mb) \
    asm volatile("cp.async.bulk.shared::cluster.global.mbarrier::complete_tx::bytes [%0], [%1], %2, [%3];" \
        :: "r"(dst), "l"(src), "r"(4096u), "r"(mb) : "memory")

__device__ __forceinline__ uint32_t swzoff(int r, int h) {
    int u = 2 * r + h;
    return (uint32_t)((u ^ ((u >> 3) & 1)) << 4);
}
__device__ __forceinline__ uint32_t hpack(float a, float b) {
    __half2 H = __halves2half2(__float2half_rn(a), __float2half_rn(b));
    return *reinterpret_cast<uint32_t*>(&H);
}
__device__ __forceinline__ uint32_t lpack(float a, float b) {
    __half ha = __float2half_rn(a), hb = __float2half_rn(b);
    __half2 L = __halves2half2(__float2half_rn(a - __half2float(ha)),
                               __float2half_rn(b - __half2float(hb)));
    return *reinterpret_cast<uint32_t*>(&L);
}

// gram smem: 3 slots x 32KB (K=32 stage); bars after
#define G_SLOT 32768
#define G_NSTG 3
#define G_BAR  (G_NSTG * G_SLOT)        // 98304
#define SMEM_G (G_BAR + 256)
// out smem: 3 slots x 32KB (K=64 stage: A0..A3, B0..B3); bars after
#define O_SLOT 32768
#define O_NSTG 3
#define O_BAR  (O_NSTG * O_SLOT)        // 98304
#define SMEM_O (O_BAR + 256)
#define SPLIT_SMEM (64 * 257 * 4)

// ---------------------------------------------------------------------------
// split: x[b][n][c] -> tiled-swizzled XcT_h, XtT_h/l
// ---------------------------------------------------------------------------
__global__ void __launch_bounds__(256) split_kernel(const float* __restrict__ x) {
    extern __shared__ float sm[];  // [64][257]
    const int n0 = blockIdx.x * 64, c0 = blockIdx.y * 256, b = blockIdx.z;
    const int t = threadIdx.x;
    const float* Xb = x + (size_t)b * NDIM * CDIM;
    #pragma unroll
    for (int r = 0; r < 64; r++) sm[r * 257 + t] = Xb[(size_t)(n0 + r) * CDIM + c0 + t];
    __syncthreads();

    {   // XcT hi
        const int rl = t & 63, chunk = t >> 6;
        const int n = n0 + rl, nt = n >> 7, r = n & 127;
        char* base = (char*)g_XcT_h + ((size_t)(b * 128 + nt) * 32) * 4096;
        #pragma unroll
        for (int q = 0; q < 4; q++) {
            const int s = (c0 >> 4) + chunk * 4 + q;
            const float* src = sm + rl * 257 + chunk * 64 + q * 16;
            uint32_t w[8];
            #pragma unroll
            for (int e = 0; e < 8; e++) w[e] = hpack(src[2 * e], src[2 * e + 1]);
            char* blk = base + (size_t)s * 4096;
            *(uint4*)(blk + swzoff(r, 0)) = make_uint4(w[0], w[1], w[2], w[3]);
            *(uint4*)(blk + swzoff(r, 1)) = make_uint4(w[4], w[5], w[6], w[7]);
        }
    }
    {   // XtT hi+lo
        const int c = c0 + t, ct = c >> 7, r = c & 127;
        const size_t tb = ((size_t)(b * 4 + ct) * 1024) * 4096;
        char* bh = (char*)g_XtT_h + tb;
        char* bl = (char*)g_XtT_l + tb;
        #pragma unroll
        for (int q = 0; q < 4; q++) {
            const int s = (n0 >> 4) + q;
            uint32_t wh[8], wl[8];
            #pragma unroll
            for (int e = 0; e < 8; e++) {
                float a = sm[(q * 16 + 2 * e) * 257 + t];
                float bvx = sm[(q * 16 + 2 * e + 1) * 257 + t];
                wh[e] = hpack(a, bvx);
                wl[e] = lpack(a, bvx);
            }
            char* kh = bh + (size_t)s * 4096;
            char* kl = bl + (size_t)s * 4096;
            *(uint4*)(kh + swzoff(r, 0)) = make_uint4(wh[0], wh[1], wh[2], wh[3]);
            *(uint4*)(kh + swzoff(r, 1)) = make_uint4(wh[4], wh[5], wh[6], wh[7]);
            *(uint4*)(kl + swzoff(r, 0)) = make_uint4(wl[0], wl[1], wl[2], wl[3]);
            *(uint4*)(kl + swzoff(r, 1)) = make_uint4(wl[4], wl[5], wl[6], wl[7]);
        }
    }
}

// ---------------------------------------------------------------------------
// gram: E = Xt Xt^T (3-pass hi/lo), K=32 stages, 3-slot bulk pipeline,
// upper-triangle tiles + 8-way K split
// ---------------------------------------------------------------------------
__global__ void __launch_bounds__(256, 2) gram_mma_kernel() {
    const int IT[10] = {0,0,0,0,1,1,1,2,2,3};
    const int JT[10] = {0,1,2,3,1,2,3,2,3,3};
    const int pi = blockIdx.x, ks = blockIdx.y, b = blockIdx.z;
    const int it = IT[pi], jt = JT[pi];
    const bool same = (it == jt);
    const int i0 = it * 128, j0 = jt * 128;

    extern __shared__ __align__(1024) char smem[];
    const int tid = threadIdx.x, lane = tid & 31;
    const int mo = ((tid >> 5) & 3) * 32, no = (tid >> 7) * 64;
    const uint32_t sbase = s2u(smem);
    const uint32_t FB = sbase + G_BAR, EB = sbase + G_BAR + 64;

    if (tid == 0) {
        #pragma unroll
        for (int k = 0; k < G_NSTG; k++) { MBI(FB + 8 * k, 1); MBI(EB + 8 * k, 256); }
    }
    __syncthreads();

    const char* pAh = (char*)g_XtT_h + ((size_t)(b * 4 + it) * 1024 + ks * KBLK) * 4096;
    const char* pAl = (char*)g_XtT_l + ((size_t)(b * 4 + it) * 1024 + ks * KBLK) * 4096;
    const char* pBh = (char*)g_XtT_h + ((size_t)(b * 4 + jt) * 1024 + ks * KBLK) * 4096;
    const char* pBl = (char*)g_XtT_l + ((size_t)(b * 4 + jt) * 1024 + ks * KBLK) * 4096;
    const uint32_t bO = same ? 0u : 16384u;
    const uint32_t tx = same ? 16384u : 32768u;
    const int nst = KSEG / 32;  // 64 stages of K=32

    #define G_ISSUE(j, slot) do {                                      \
        uint32_t dst = sbase + (uint32_t)(slot) * G_SLOT;              \
        uint32_t mb = FB + (slot) * 8;                                 \
        MBX(mb, tx);                                                   \
        BULK(dst,         pAh + (size_t)(2*(j))   * 4096, mb);         \
        BULK(dst + 4096,  pAh + (size_t)(2*(j)+1) * 4096, mb);         \
        BULK(dst + 8192,  pAl + (size_t)(2*(j))   * 4096, mb);         \
        BULK(dst + 12288, pAl + (size_t)(2*(j)+1) * 4096, mb);         \
        if (!same) {                                                   \
            BULK(dst + 16384, pBh + (size_t)(2*(j))   * 4096, mb);     \
            BULK(dst + 20480, pBh + (size_t)(2*(j)+1) * 4096, mb);     \
            BULK(dst + 24576, pBl + (size_t)(2*(j))   * 4096, mb);     \
            BULK(dst + 28672, pBl + (size_t)(2*(j)+1) * 4096, mb);     \
        }                                                              \
    } while (0)

    if (tid == 0) { G_ISSUE(0, 0); G_ISSUE(1, 1); }

    const uint32_t swzA = swzoff(lane & 15, lane >> 4);
    const uint32_t swzB = swzoff((lane & 7) + ((lane >> 4) & 1) * 8, (lane >> 3) & 1);

    float acc[2][8][4];
    #pragma unroll
    for (int i = 0; i < 2; i++)
        #pragma unroll
        for (int j = 0; j < 8; j++)
            #pragma unroll
            for (int q = 0; q < 4; q++) acc[i][j][q] = 0.0f;

    int cslot = 0, cph = 0;
    int pslot = G_NSTG - 1;
    int eslot = 0, eph = 0;

    for (int s = 0; s < nst; s++) {
        MBW(FB + cslot * 8, cph);
        const uint32_t bb = sbase + (uint32_t)cslot * G_SLOT;

        #pragma unroll
        for (int kh = 0; kh < 2; kh++) {
            const uint32_t ra_h = bb + (uint32_t)kh * 4096;
            const uint32_t ra_l = bb + 8192 + (uint32_t)kh * 4096;
            const uint32_t rbh = bb + bO + (uint32_t)kh * 4096;
            const uint32_t rbl = bb + bO + 8192 + (uint32_t)kh * 4096;

            uint32_t ah[2][4], al[2][4];
            #pragma unroll
            for (int mi = 0; mi < 2; mi++) {
                uint32_t ro = (uint32_t)(mo + mi * 16) * 32;
                ldm4(ah[mi], ra_h + ro + swzA);
                ldm4(al[mi], ra_l + ro + swzA);
            }
            uint32_t bhp[2][4], blp[2][4];
            ldm4(bhp[0], rbh + (uint32_t)no * 32 + swzB);
            ldm4(blp[0], rbl + (uint32_t)no * 32 + swzB);
            #pragma unroll
            for (int p = 0; p < 4; p++) {
                if (p < 3) {
                    uint32_t ro = (uint32_t)(no + (p + 1) * 16) * 32;
                    ldm4(bhp[(p + 1) & 1], rbh + ro + swzB);
                    ldm4(blp[(p + 1) & 1], rbl + ro + swzB);
                }
                uint32_t* ch = bhp[p & 1];
                uint32_t* cl = blp[p & 1];
                #pragma unroll
                for (int hf = 0; hf < 2; hf++) {
                    int ni = p * 2 + hf;
                    #pragma unroll
                    for (int mi = 0; mi < 2; mi++) {
                        mma16816(acc[mi][ni], ah[mi], ch + hf * 2);
                        mma16816(acc[mi][ni], ah[mi], cl + hf * 2);
                        mma16816(acc[mi][ni], al[mi], ch + hf * 2);
                    }
                }
            }
        }
        MBA(EB + cslot * 8);
        if (++cslot == G_NSTG) { cslot = 0; cph ^= 1; }

        if (tid == 0) {
            int j = s + G_NSTG - 1;
            if (j < nst) {
                if (j >= G_NSTG) {
                    MBW(EB + eslot * 8, eph);
                    if (++eslot == G_NSTG) { eslot = 0; eph ^= 1; }
                }
                G_ISSUE(j, pslot);
                if (++pslot == G_NSTG) pslot = 0;
            }
        }
    }
    #undef G_ISSUE

    // epilogue: Epart + mirror
    const int er = lane >> 2, ec = (lane & 3) * 2;
    float* Ep = g_Epart + (((size_t)ks * BATCH + b) * CDIM + i0) * CDIM + j0;
    #pragma unroll
    for (int mi = 0; mi < 2; mi++)
        #pragma unroll
        for (int ni = 0; ni < 8; ni++) {
            int r0 = mo + mi * 16 + er;
            int c  = no + ni * 8 + ec;
            *(float2*)(Ep + (size_t)r0 * CDIM + c)       = make_float2(acc[mi][ni][0], acc[mi][ni][1]);
            *(float2*)(Ep + (size_t)(r0 + 8) * CDIM + c) = make_float2(acc[mi][ni][2], acc[mi][ni][3]);
        }

    if (!same) {
        float* ts = (float*)smem;  // stride 132, reuses pipeline smem (all consumed)
        __syncthreads();
        #pragma unroll
        for (int mi = 0; mi < 2; mi++)
            #pragma unroll
            for (int ni = 0; ni < 8; ni++) {
                int r0 = mo + mi * 16 + er, c = no + ni * 8 + ec;
                ts[r0 * 132 + c]           = acc[mi][ni][0];
                ts[r0 * 132 + c + 1]       = acc[mi][ni][1];
                ts[(r0 + 8) * 132 + c]     = acc[mi][ni][2];
                ts[(r0 + 8) * 132 + c + 1] = acc[mi][ni][3];
            }
        __syncthreads();
        float* Em = g_Epart + (((size_t)ks * BATCH + b) * CDIM + j0) * CDIM + i0;
        const int j = tid >> 1, hf = tid & 1;
        float* dst = Em + (size_t)j * CDIM + hf * 64;
        #pragma unroll
        for (int w = 0; w < 16; w++) {
            float4 v = make_float4(ts[(hf * 64 + 4 * w) * 132 + j],
                                   ts[(hf * 64 + 4 * w + 1) * 132 + j],
                                   ts[(hf * 64 + 4 * w + 2) * 132 + j],
                                   ts[(hf * 64 + 4 * w + 3) * 132 + j]);
            *(float4*)(dst + 4 * w) = v;
        }
    }
}

// ---------------------------------------------------------------------------
// out: Y = Xc_h * M'^T + x_hi, K=64 stages, 3-slot bulk pipeline.
// K-loop rotated so the last two stages cover channels [i0, i0+128):
// residual hi read from smem slots 0/1 (no fp32 x re-read).
// ---------------------------------------------------------------------------
__global__ void __launch_bounds__(256, 2) out_mma_kernel(float* __restrict__ y) {
    extern __shared__ __align__(1024) char smem[];
    const int nt = blockIdx.x, itile = blockIdx.y, b = blockIdx.z;
    const int n0 = nt * 128, i0 = itile * 128;
    const int tid = threadIdx.x, lane = tid & 31;
    const int mo = ((tid >> 5) & 3) * 32, no = (tid >> 7) * 64;
    const uint32_t sbase = s2u(smem);
    const uint32_t FB = sbase + O_BAR, EB = sbase + O_BAR + 64;

    if (tid == 0) {
        #pragma unroll
        for (int k = 0; k < O_NSTG; k++) { MBI(FB + 8 * k, 1); MBI(EB + 8 * k, 256); }
    }
    __syncthreads();

    const char* pA = (char*)g_XcT_h + ((size_t)(b * 128 + nt) * 32) * 4096;
    const char* pB = (char*)g_MT_h + ((size_t)(b * 4 + itile) * 32) * 4096;
    const int nst = CDIM / 64;  // 8 stages of K=64
    const int first = (2 * itile + 2) & 7;   // rotation start

    #define O_ISSUE(j, slot) do {                                      \
        int stg = ((j) + first) & 7;                                   \
        uint32_t dst = sbase + (uint32_t)(slot) * O_SLOT;              \
        uint32_t mb = FB + (slot) * 8;                                 \
        MBX(mb, 32768u);                                               \
        BULK(dst,         pA + (size_t)(4*stg)   * 4096, mb);          \
        BULK(dst + 4096,  pA + (size_t)(4*stg+1) * 4096, mb);          \
        BULK(dst + 8192,  pA + (size_t)(4*stg+2) * 4096, mb);          \
        BULK(dst + 12288, pA + (size_t)(4*stg+3) * 4096, mb);          \
        BULK(dst + 16384, pB + (size_t)(4*stg)   * 4096, mb);          \
        BULK(dst + 20480, pB + (size_t)(4*stg+1) * 4096, mb);          \
        BULK(dst + 24576, pB + (size_t)(4*stg+2) * 4096, mb);          \
        BULK(dst + 28672, pB + (size_t)(4*stg+3) * 4096, mb);          \
    } while (0)

    if (tid == 0) { O_ISSUE(0, 0); O_ISSUE(1, 1); }

    const uint32_t swzA = swzoff(lane & 15, lane >> 4);
    const uint32_t swzB = swzoff((lane & 7) + ((lane >> 4) & 1) * 8, (lane >> 3) & 1);

    float acc[2][8][4];
    #pragma unroll
    for (int i = 0; i < 2; i++)
        #pragma unroll
        for (int j = 0; j < 8; j++)
            #pragma unroll
            for (int q = 0; q < 4; q++) acc[i][j][q] = 0.0f;

    int cslot = 0, cph = 0;
    int pslot = O_NSTG - 1;
    int eslot = 0, eph = 0;

    for (int s = 0; s < nst; s++) {
        MBW(FB + cslot * 8, cph);
        const uint32_t bb = sbase + (uint32_t)cslot * O_SLOT;

        #pragma unroll
        for (int kh = 0; kh < 4; kh++) {
            const uint32_t ra = bb + (uint32_t)kh * 4096;
            const uint32_t rb = bb + 16384 + (uint32_t)kh * 4096;
            uint32_t ah[2][4];
            #pragma unroll
            for (int mi = 0; mi < 2; mi++)
                ldm4(ah[mi], ra + (uint32_t)(mo + mi * 16) * 32 + swzA);
            uint32_t bhp[2][4];
            ldm4(bhp[0], rb + (uint32_t)no * 32 + swzB);
            #pragma unroll
            for (int p = 0; p < 4; p++) {
                if (p < 3)
                    ldm4(bhp[(p + 1) & 1], rb + (uint32_t)(no + (p + 1) * 16) * 32 + swzB);
                uint32_t* ch = bhp[p & 1];
                #pragma unroll
                for (int hf = 0; hf < 2; hf++) {
                    int ni = p * 2 + hf;
                    #pragma unroll
                    for (int mi = 0; mi < 2; mi++)
                        mma16816(acc[mi][ni], ah[mi], ch + hf * 2);
                }
            }
        }
        MBA(EB + cslot * 8);
        if (++cslot == O_NSTG) { cslot = 0; cph ^= 1; }

        if (tid == 0) {
            int j = s + O_NSTG - 1;
            if (j < nst) {
                if (j >= O_NSTG) {
                    MBW(EB + eslot * 8, eph);
                    if (++eslot == O_NSTG) { eslot = 0; eph ^= 1; }
                }
                O_ISSUE(j, pslot);
                if (++pslot == O_NSTG) pslot = 0;
            }
        }
    }
    #undef O_ISSUE

    // epilogue: residual hi from smem (slots 0,1 hold channels [i0, i0+128))
    float* yr = y + ((size_t)b * NDIM + n0) * CDIM + i0;
    const int er = lane >> 2, ec = (lane & 3) * 2;
    #pragma unroll
    for (int mi = 0; mi < 2; mi++)
        #pragma unroll
        for (int ni = 0; ni < 8; ni++) {
            int r0 = mo + mi * 16 + er;
            int c  = no + ni * 8 + ec;
            uint32_t sl  = (uint32_t)(c >> 6);
            uint32_t blk = (uint32_t)((c & 63) >> 4);
            uint32_t hu  = (uint32_t)((c & 15) >> 3);
            uint32_t el  = (uint32_t)(c & 7);
            uint32_t base = sbase + sl * O_SLOT + blk * 4096u;
            uint32_t w0, w1;
            asm volatile("ld.shared.b32 %0, [%1];" : "=r"(w0)
                         : "r"(base + swzoff(r0, (int)hu) + el * 2));
            asm volatile("ld.shared.b32 %0, [%1];" : "=r"(w1)
                         : "r"(base + swzoff(r0 + 8, (int)hu) + el * 2));
            __half2 x0 = *reinterpret_cast<__half2*>(&w0);
            __half2 x1 = *reinterpret_cast<__half2*>(&w1);
            *(float2*)(yr + (size_t)r0 * CDIM + c) =
                make_float2(acc[mi][ni][0] + __low2float(x0),
                            acc[mi][ni][1] + __high2float(x0));
            *(float2*)(yr + (size_t)(r0 + 8) * CDIM + c) =
                make_float2(acc[mi][ni][2] + __low2float(x1),
                            acc[mi][ni][3] + __high2float(x1));
        }
}

// ---------------------------------------------------------------------------
// softmax(-E) over summed K-partials; writes tiled-swizzled M' = gamma*att
// ---------------------------------------------------------------------------
__global__ void __launch_bounds__(256) softmax_kernel(const float* __restrict__ gp) {
    const int i = blockIdx.x, b = blockIdx.y;
    __shared__ float sm[256];
    __shared__ __half hrow[512];
    const int t = threadIdx.x;
    float v0 = 0.0f, v1 = 0.0f;
    #pragma unroll
    for (int ks = 0; ks < KSPLIT; ks++) {
        const float* e = g_Epart + (((size_t)ks * BATCH + b) * CDIM + i) * CDIM;
        v0 += e[t];
        v1 += e[t + 256];
    }
    sm[t] = fminf(v0, v1);
    __syncthreads();
    for (int s = 128; s > 0; s >>= 1) { if (t < s) sm[t] = fminf(sm[t], sm[t + s]); __syncthreads(); }
    float mn = sm[0];
    __syncthreads();
    float w0 = __expf(mn - v0), w1 = __expf(mn - v1);
    sm[t] = w0 + w1;
    __syncthreads();
    for (int s = 128; s > 0; s >>= 1) { if (t < s) sm[t] += sm[t + s]; __syncthreads(); }
    float inv = gp[0] / sm[0];
    hrow[t]       = __float2half_rn(w0 * inv);
    hrow[t + 256] = __float2half_rn(w1 * inv);
    __syncthreads();
    if (t < 64) {
        const int s = t >> 1, h = t & 1;
        const __half* src = hrow + s * 16 + h * 8;
        uint32_t w[4];
        #pragma unroll
        for (int e = 0; e < 4; e++) w[e] = *(const uint32_t*)(src + 2 * e);
        char* blk = (char*)g_MT_h + ((size_t)(b * 4 + (i >> 7)) * 32 + s) * 4096;
        *(uint4*)(blk + swzoff(i & 127, h)) = make_uint4(w[0], w[1], w[2], w[3]);
    }
}

extern "C" void kernel_launch(void* const* d_in, const int* in_sizes, int n_in,
                              void* d_out, int out_size) {
    const float* x  = (const float*)d_in[0];
    const float* gm = (const float*)d_in[1];
    float*       y  = (float*)d_out;
    (void)in_sizes; (void)n_in; (void)out_size;

    cudaFuncSetAttribute(split_kernel,    cudaFuncAttributeMaxDynamicSharedMemorySize, SPLIT_SMEM);
    cudaFuncSetAttribute(gram_mma_kernel, cudaFuncAttributeMaxDynamicSharedMemorySize, SMEM_G);
    cudaFuncSetAttribute(out_mma_kernel,  cudaFuncAttributeMaxDynamicSharedMemorySize, SMEM_O);

    split_kernel<<<dim3(NDIM / 64, CDIM / 256, BATCH), 256, SPLIT_SMEM>>>(x);
    gram_mma_kernel<<<dim3(10, KSPLIT, BATCH), 256, SMEM_G>>>();
    softmax_kernel<<<dim3(CDIM, BATCH), 256>>>(gm);
    out_mma_kernel<<<dim3(NDIM / 128, 4, BATCH), 256, SMEM_O>>>(y);
}

// round 16
// speedup vs baseline: 1.0095x; 1.0095x over previous
#include <cuda_runtime.h>
#include <cuda_fp16.h>
#include <cstdint>

#define BATCH 8
#define NDIM  16384
#define CDIM  512
#define KSPLIT 16
#define KSEG  (NDIM / KSPLIT)   // 1024

// Tiled-swizzled operand storage: one 4096B block per (128-tile, K=16 stage).
// Block = 128 rows x 16 halves; unit u = 2*r + h (16B), at ((u ^ ((u>>3)&1)) << 4).
__device__ __half g_XtT_h[(size_t)BATCH * 4 * 1024 * 2048];  // [b][ct][nstage]
__device__ __half g_XtT_l[(size_t)BATCH * 4 * 1024 * 2048];
__device__ __half g_XcT_h[(size_t)BATCH * 128 * 32 * 2048];  // [b][nt][cstage]
__device__ __half g_MT_h [(size_t)BATCH * 4 * 32 * 2048];    // [b][it][cstage]
__device__ float  g_Epart[(size_t)KSPLIT * BATCH * CDIM * CDIM];

// ---- helpers -------------------------------------------------------------
__device__ __forceinline__ uint32_t s2u(const void* p) {
    uint32_t a;
    asm("{ .reg .u64 t; cvta.to.shared.u64 t, %1; cvt.u32.u64 %0, t; }" : "=r"(a) : "l"(p));
    return a;
}
__device__ __forceinline__ void ldm4(uint32_t* r, uint32_t a) {
    asm volatile("ldmatrix.sync.aligned.m8n8.x4.shared.b16 {%0,%1,%2,%3},[%4];"
                 : "=r"(r[0]), "=r"(r[1]), "=r"(r[2]), "=r"(r[3]) : "r"(a));
}
__device__ __forceinline__ void mma16816(float* d, const uint32_t* a, const uint32_t* b) {
    asm volatile("mma.sync.aligned.m16n8k16.row.col.f32.f16.f16.f32 "
                 "{%0,%1,%2,%3},{%4,%5,%6,%7},{%8,%9},{%0,%1,%2,%3};"
                 : "+f"(d[0]), "+f"(d[1]), "+f"(d[2]), "+f"(d[3])
                 : "r"(a[0]), "r"(a[1]), "r"(a[2]), "r"(a[3]), "r"(b[0]), "r"(b[1]));
}
#define MBI(a, n) asm volatile("mbarrier.init.shared.b64 [%0], %1;" :: "r"(a), "r"((uint32_t)(n)) : "memory")
#define MBA(a)    asm volatile("mbarrier.arrive.shared.b64 _, [%0];" :: "r"(a) : "memory")
#define MBX(a, tx) asm volatile("mbarrier.arrive.expect_tx.shared.b64 _, [%0], %1;" :: "r"(a), "r"((uint32_t)(tx)) : "memory")
#define MBW(a, p) do { \
    asm volatile("{\n\t.reg .pred P;\n\tWL_%=:\n\t" \
        "mbarrier.try_wait.parity.acquire.cta.shared::cta.b64 P, [%0], %1, 0x989680;\n\t" \
        "@P bra.uni WD_%=;\n\tbra.uni WL_%=;\n\tWD_%=:\n\t}" \
        :: "r"(a), "r"((uint32_t)(p)) : "memory"); } while (0)
#define BULK(dst, src, mb) \
    asm volatile("cp.async.bulk.shared::cluster.global.mbarrier::complete_tx::bytes [%0], [%1], %2, [%3];" \
        :: "r"(dst), "l"(src), "r"(4096u), "r"(mb) : "memory")

__device__ __forceinline__ uint32_t swzoff(int r, int h) {
    int u = 2 * r + h;
    return (uint32_t)((u ^ ((u >> 3) & 1)) << 4);
}
__device__ __forceinline__ uint32_t hpack(float a, float b) {
    __half2 H = __halves2half2(__float2half_rn(a), __float2half_rn(b));
    return *reinterpret_cast<uint32_t*>(&H);
}
__device__ __forceinline__ uint32_t lpack(float a, float b) {
    __half ha = __float2half_rn(a), hb = __float2half_rn(b);
    __half2 L = __halves2half2(__float2half_rn(a - __half2float(ha)),
                               __float2half_rn(b - __half2float(hb)));
    return *reinterpret_cast<uint32_t*>(&L);
}

// gram smem: 3 slots x 32KB (K=32 stage); bars after
#define G_SLOT 32768
#define G_NSTG 3
#define G_BAR  (G_NSTG * G_SLOT)        // 98304
#define SMEM_G (G_BAR + 256)
// out smem: 3 slots x 32KB (K=64 stage: A0..A3, B0..B3); bars after
#define O_SLOT 32768
#define O_NSTG 3
#define O_BAR  (O_NSTG * O_SLOT)        // 98304
#define SMEM_O (O_BAR + 256)
#define SPLIT_SMEM (64 * 257 * 4)

// ---------------------------------------------------------------------------
// split: x[b][n][c] -> tiled-swizzled XcT_h, XtT_h/l
// ---------------------------------------------------------------------------
__global__ void __launch_bounds__(256) split_kernel(const float* __restrict__ x) {
    extern __shared__ float sm[];  // [64][257]
    const int n0 = blockIdx.x * 64, c0 = blockIdx.y * 256, b = blockIdx.z;
    const int t = threadIdx.x;
    const float* Xb = x + (size_t)b * NDIM * CDIM;
    #pragma unroll
    for (int r = 0; r < 64; r++) sm[r * 257 + t] = Xb[(size_t)(n0 + r) * CDIM + c0 + t];
    __syncthreads();

    {   // XcT hi
        const int rl = t & 63, chunk = t >> 6;
        const int n = n0 + rl, nt = n >> 7, r = n & 127;
        char* base = (char*)g_XcT_h + ((size_t)(b * 128 + nt) * 32) * 4096;
        #pragma unroll
        for (int q = 0; q < 4; q++) {
            const int s = (c0 >> 4) + chunk * 4 + q;
            const float* src = sm + rl * 257 + chunk * 64 + q * 16;
            uint32_t w[8];
            #pragma unroll
            for (int e = 0; e < 8; e++) w[e] = hpack(src[2 * e], src[2 * e + 1]);
            char* blk = base + (size_t)s * 4096;
            *(uint4*)(blk + swzoff(r, 0)) = make_uint4(w[0], w[1], w[2], w[3]);
            *(uint4*)(blk + swzoff(r, 1)) = make_uint4(w[4], w[5], w[6], w[7]);
        }
    }
    {   // XtT hi+lo
        const int c = c0 + t, ct = c >> 7, r = c & 127;
        const size_t tb = ((size_t)(b * 4 + ct) * 1024) * 4096;
        char* bh = (char*)g_XtT_h + tb;
        char* bl = (char*)g_XtT_l + tb;
        #pragma unroll
        for (int q = 0; q < 4; q++) {
            const int s = (n0 >> 4) + q;
            uint32_t wh[8], wl[8];
            #pragma unroll
            for (int e = 0; e < 8; e++) {
                float a = sm[(q * 16 + 2 * e) * 257 + t];
                float bvx = sm[(q * 16 + 2 * e + 1) * 257 + t];
                wh[e] = hpack(a, bvx);
                wl[e] = lpack(a, bvx);
            }
            char* kh = bh + (size_t)s * 4096;
            char* kl = bl + (size_t)s * 4096;
            *(uint4*)(kh + swzoff(r, 0)) = make_uint4(wh[0], wh[1], wh[2], wh[3]);
            *(uint4*)(kh + swzoff(r, 1)) = make_uint4(wh[4], wh[5], wh[6], wh[7]);
            *(uint4*)(kl + swzoff(r, 0)) = make_uint4(wl[0], wl[1], wl[2], wl[3]);
            *(uint4*)(kl + swzoff(r, 1)) = make_uint4(wl[4], wl[5], wl[6], wl[7]);
        }
    }
}

// ---------------------------------------------------------------------------
// gram: E = Xt Xt^T (3-pass hi/lo), K=32 stages, 3-slot bulk pipeline,
// upper-triangle tiles + 16-way K split
// ---------------------------------------------------------------------------
__global__ void __launch_bounds__(256, 2) gram_mma_kernel() {
    const int IT[10] = {0,0,0,0,1,1,1,2,2,3};
    const int JT[10] = {0,1,2,3,1,2,3,2,3,3};
    const int pi = blockIdx.x, ks = blockIdx.y, b = blockIdx.z;
    const int it = IT[pi], jt = JT[pi];
    const bool same = (it == jt);
    const int i0 = it * 128, j0 = jt * 128;

    extern __shared__ __align__(1024) char smem[];
    const int tid = threadIdx.x, lane = tid & 31;
    const int mo = ((tid >> 5) & 3) * 32, no = (tid >> 7) * 64;
    const uint32_t sbase = s2u(smem);
    const uint32_t FB = sbase + G_BAR, EB = sbase + G_BAR + 64;

    if (tid == 0) {
        #pragma unroll
        for (int k = 0; k < G_NSTG; k++) { MBI(FB + 8 * k, 1); MBI(EB + 8 * k, 256); }
    }
    __syncthreads();

    const char* pAh = (char*)g_XtT_h + ((size_t)(b * 4 + it) * 1024 + ks * 64) * 4096;
    const char* pAl = (char*)g_XtT_l + ((size_t)(b * 4 + it) * 1024 + ks * 64) * 4096;
    const char* pBh = (char*)g_XtT_h + ((size_t)(b * 4 + jt) * 1024 + ks * 64) * 4096;
    const char* pBl = (char*)g_XtT_l + ((size_t)(b * 4 + jt) * 1024 + ks * 64) * 4096;
    const uint32_t bO = same ? 0u : 16384u;
    const uint32_t tx = same ? 16384u : 32768u;
    const int nst = KSEG / 32;  // 32 stages of K=32

    #define G_ISSUE(j, slot) do {                                      \
        uint32_t dst = sbase + (uint32_t)(slot) * G_SLOT;              \
        uint32_t mb = FB + (slot) * 8;                                 \
        MBX(mb, tx);                                                   \
        BULK(dst,         pAh + (size_t)(2*(j))   * 4096, mb);         \
        BULK(dst + 4096,  pAh + (size_t)(2*(j)+1) * 4096, mb);         \
        BULK(dst + 8192,  pAl + (size_t)(2*(j))   * 4096, mb);         \
        BULK(dst + 12288, pAl + (size_t)(2*(j)+1) * 4096, mb);         \
        if (!same) {                                                   \
            BULK(dst + 16384, pBh + (size_t)(2*(j))   * 4096, mb);     \
            BULK(dst + 20480, pBh + (size_t)(2*(j)+1) * 4096, mb);     \
            BULK(dst + 24576, pBl + (size_t)(2*(j))   * 4096, mb);     \
            BULK(dst + 28672, pBl + (size_t)(2*(j)+1) * 4096, mb);     \
        }                                                              \
    } while (0)

    if (tid == 0) { G_ISSUE(0, 0); G_ISSUE(1, 1); }

    const uint32_t swzA = swzoff(lane & 15, lane >> 4);
    const uint32_t swzB = swzoff((lane & 7) + ((lane >> 4) & 1) * 8, (lane >> 3) & 1);

    float acc[2][8][4];
    #pragma unroll
    for (int i = 0; i < 2; i++)
        #pragma unroll
        for (int j = 0; j < 8; j++)
            #pragma unroll
            for (int q = 0; q < 4; q++) acc[i][j][q] = 0.0f;

    int cslot = 0, cph = 0;
    int pslot = G_NSTG - 1;
    int eslot = 0, eph = 0;

    for (int s = 0; s < nst; s++) {
        MBW(FB + cslot * 8, cph);
        const uint32_t bb = sbase + (uint32_t)cslot * G_SLOT;

        #pragma unroll
        for (int kh = 0; kh < 2; kh++) {
            const uint32_t ra_h = bb + (uint32_t)kh * 4096;
            const uint32_t ra_l = bb + 8192 + (uint32_t)kh * 4096;
            const uint32_t rbh = bb + bO + (uint32_t)kh * 4096;
            const uint32_t rbl = bb + bO + 8192 + (uint32_t)kh * 4096;

            uint32_t ah[2][4], al[2][4];
            #pragma unroll
            for (int mi = 0; mi < 2; mi++) {
                uint32_t ro = (uint32_t)(mo + mi * 16) * 32;
                ldm4(ah[mi], ra_h + ro + swzA);
                ldm4(al[mi], ra_l + ro + swzA);
            }
            uint32_t bhp[2][4], blp[2][4];
            ldm4(bhp[0], rbh + (uint32_t)no * 32 + swzB);
            ldm4(blp[0], rbl + (uint32_t)no * 32 + swzB);
            #pragma unroll
            for (int p = 0; p < 4; p++) {
                if (p < 3) {
                    uint32_t ro = (uint32_t)(no + (p + 1) * 16) * 32;
                    ldm4(bhp[(p + 1) & 1], rbh + ro + swzB);
                    ldm4(blp[(p + 1) & 1], rbl + ro + swzB);
                }
                uint32_t* ch = bhp[p & 1];
                uint32_t* cl = blp[p & 1];
                #pragma unroll
                for (int hf = 0; hf < 2; hf++) {
                    int ni = p * 2 + hf;
                    #pragma unroll
                    for (int mi = 0; mi < 2; mi++) {
                        mma16816(acc[mi][ni], ah[mi], ch + hf * 2);
                        mma16816(acc[mi][ni], ah[mi], cl + hf * 2);
                        mma16816(acc[mi][ni], al[mi], ch + hf * 2);
                    }
                }
            }
        }
        MBA(EB + cslot * 8);
        if (++cslot == G_NSTG) { cslot = 0; cph ^= 1; }

        if (tid == 0) {
            int j = s + G_NSTG - 1;
            if (j < nst) {
                if (j >= G_NSTG) {
                    MBW(EB + eslot * 8, eph);
                    if (++eslot == G_NSTG) { eslot = 0; eph ^= 1; }
                }
                G_ISSUE(j, pslot);
                if (++pslot == G_NSTG) pslot = 0;
            }
        }
    }
    #undef G_ISSUE

    // epilogue: Epart + mirror
    const int er = lane >> 2, ec = (lane & 3) * 2;
    float* Ep = g_Epart + (((size_t)ks * BATCH + b) * CDIM + i0) * CDIM + j0;
    #pragma unroll
    for (int mi = 0; mi < 2; mi++)
        #pragma unroll
        for (int ni = 0; ni < 8; ni++) {
            int r0 = mo + mi * 16 + er;
            int c  = no + ni * 8 + ec;
            *(float2*)(Ep + (size_t)r0 * CDIM + c)       = make_float2(acc[mi][ni][0], acc[mi][ni][1]);
            *(float2*)(Ep + (size_t)(r0 + 8) * CDIM + c) = make_float2(acc[mi][ni][2], acc[mi][ni][3]);
        }

    if (!same) {
        float* ts = (float*)smem;  // stride 132, reuses pipeline smem (all consumed)
        __syncthreads();
        #pragma unroll
        for (int mi = 0; mi < 2; mi++)
            #pragma unroll
            for (int ni = 0; ni < 8; ni++) {
                int r0 = mo + mi * 16 + er, c = no + ni * 8 + ec;
                ts[r0 * 132 + c]           = acc[mi][ni][0];
                ts[r0 * 132 + c + 1]       = acc[mi][ni][1];
                ts[(r0 + 8) * 132 + c]     = acc[mi][ni][2];
                ts[(r0 + 8) * 132 + c + 1] = acc[mi][ni][3];
            }
        __syncthreads();
        float* Em = g_Epart + (((size_t)ks * BATCH + b) * CDIM + j0) * CDIM + i0;
        const int j = tid >> 1, hf = tid & 1;
        float* dst = Em + (size_t)j * CDIM + hf * 64;
        #pragma unroll
        for (int w = 0; w < 16; w++) {
            float4 v = make_float4(ts[(hf * 64 + 4 * w) * 132 + j],
                                   ts[(hf * 64 + 4 * w + 1) * 132 + j],
                                   ts[(hf * 64 + 4 * w + 2) * 132 + j],
                                   ts[(hf * 64 + 4 * w + 3) * 132 + j]);
            *(float4*)(dst + 4 * w) = v;
        }
    }
}

// ---------------------------------------------------------------------------
// out: Y = Xc_h * M'^T + x_hi, K=64 stages, 3-slot bulk pipeline.
// K-loop rotated so the last two stages cover channels [i0, i0+128):
// residual hi read from smem slots 0/1 (no fp32 x re-read).
// ---------------------------------------------------------------------------
__global__ void __launch_bounds__(256, 2) out_mma_kernel(float* __restrict__ y) {
    extern __shared__ __align__(1024) char smem[];
    const int nt = blockIdx.x, itile = blockIdx.y, b = blockIdx.z;
    const int n0 = nt * 128, i0 = itile * 128;
    const int tid = threadIdx.x, lane = tid & 31;
    const int mo = ((tid >> 5) & 3) * 32, no = (tid >> 7) * 64;
    const uint32_t sbase = s2u(smem);
    const uint32_t FB = sbase + O_BAR, EB = sbase + O_BAR + 64;

    if (tid == 0) {
        #pragma unroll
        for (int k = 0; k < O_NSTG; k++) { MBI(FB + 8 * k, 1); MBI(EB + 8 * k, 256); }
    }
    __syncthreads();

    const char* pA = (char*)g_XcT_h + ((size_t)(b * 128 + nt) * 32) * 4096;
    const char* pB = (char*)g_MT_h + ((size_t)(b * 4 + itile) * 32) * 4096;
    const int nst = CDIM / 64;  // 8 stages of K=64
    const int first = (2 * itile + 2) & 7;   // rotation start

    #define O_ISSUE(j, slot) do {                                      \
        int stg = ((j) + first) & 7;                                   \
        uint32_t dst = sbase + (uint32_t)(slot) * O_SLOT;              \
        uint32_t mb = FB + (slot) * 8;                                 \
        MBX(mb, 32768u);                                               \
        BULK(dst,         pA + (size_t)(4*stg)   * 4096, mb);          \
        BULK(dst + 4096,  pA + (size_t)(4*stg+1) * 4096, mb);          \
        BULK(dst + 8192,  pA + (size_t)(4*stg+2) * 4096, mb);          \
        BULK(dst + 12288, pA + (size_t)(4*stg+3) * 4096, mb);          \
        BULK(dst + 16384, pB + (size_t)(4*stg)   * 4096, mb);          \
        BULK(dst + 20480, pB + (size_t)(4*stg+1) * 4096, mb);          \
        BULK(dst + 24576, pB + (size_t)(4*stg+2) * 4096, mb);          \
        BULK(dst + 28672, pB + (size_t)(4*stg+3) * 4096, mb);          \
    } while (0)

    if (tid == 0) { O_ISSUE(0, 0); O_ISSUE(1, 1); }

    const uint32_t swzA = swzoff(lane & 15, lane >> 4);
    const uint32_t swzB = swzoff((lane & 7) + ((lane >> 4) & 1) * 8, (lane >> 3) & 1);

    float acc[2][8][4];
    #pragma unroll
    for (int i = 0; i < 2; i++)
        #pragma unroll
        for (int j = 0; j < 8; j++)
            #pragma unroll
            for (int q = 0; q < 4; q++) acc[i][j][q] = 0.0f;

    int cslot = 0, cph = 0;
    int pslot = O_NSTG - 1;
    int eslot = 0, eph = 0;

    for (int s = 0; s < nst; s++) {
        MBW(FB + cslot * 8, cph);
        const uint32_t bb = sbase + (uint32_t)cslot * O_SLOT;

        #pragma unroll
        for (int kh = 0; kh < 4; kh++) {
            const uint32_t ra = bb + (uint32_t)kh * 4096;
            const uint32_t rb = bb + 16384 + (uint32_t)kh * 4096;
            uint32_t ah[2][4];
            #pragma unroll
            for (int mi = 0; mi < 2; mi++)
                ldm4(ah[mi], ra + (uint32_t)(mo + mi * 16) * 32 + swzA);
            uint32_t bhp[2][4];
            ldm4(bhp[0], rb + (uint32_t)no * 32 + swzB);
            #pragma unroll
            for (int p = 0; p < 4; p++) {
                if (p < 3)
                    ldm4(bhp[(p + 1) & 1], rb + (uint32_t)(no + (p + 1) * 16) * 32 + swzB);
                uint32_t* ch = bhp[p & 1];
                #pragma unroll
                for (int hf = 0; hf < 2; hf++) {
                    int ni = p * 2 + hf;
                    #pragma unroll
                    for (int mi = 0; mi < 2; mi++)
                        mma16816(acc[mi][ni], ah[mi], ch + hf * 2);
                }
            }
        }
        MBA(EB + cslot * 8);
        if (++cslot == O_NSTG) { cslot = 0; cph ^= 1; }

        if (tid == 0) {
            int j = s + O_NSTG - 1;
            if (j < nst) {
                if (j >= O_NSTG) {
                    MBW(EB + eslot * 8, eph);
                    if (++eslot == O_NSTG) { eslot = 0; eph ^= 1; }
                }
                O_ISSUE(j, pslot);
                if (++pslot == O_NSTG) pslot = 0;
            }
        }
    }
    #undef O_ISSUE

    // epilogue: residual hi from smem (slots 0,1 hold channels [i0, i0+128))
    float* yr = y + ((size_t)b * NDIM + n0) * CDIM + i0;
    const int er = lane >> 2, ec = (lane & 3) * 2;
    #pragma unroll
    for (int mi = 0; mi < 2; mi++)
        #pragma unroll
        for (int ni = 0; ni < 8; ni++) {
            int r0 = mo + mi * 16 + er;
            int c  = no + ni * 8 + ec;
            uint32_t sl  = (uint32_t)(c >> 6);
            uint32_t blk = (uint32_t)((c & 63) >> 4);
            uint32_t hu  = (uint32_t)((c & 15) >> 3);
            uint32_t el  = (uint32_t)(c & 7);
            uint32_t base = sbase + sl * O_SLOT + blk * 4096u;
            uint32_t w0, w1;
            asm volatile("ld.shared.b32 %0, [%1];" : "=r"(w0)
                         : "r"(base + swzoff(r0, (int)hu) + el * 2));
            asm volatile("ld.shared.b32 %0, [%1];" : "=r"(w1)
                         : "r"(base + swzoff(r0 + 8, (int)hu) + el * 2));
            __half2 x0 = *reinterpret_cast<__half2*>(&w0);
            __half2 x1 = *reinterpret_cast<__half2*>(&w1);
            *(float2*)(yr + (size_t)r0 * CDIM + c) =
                make_float2(acc[mi][ni][0] + __low2float(x0),
                            acc[mi][ni][1] + __high2float(x0));
            *(float2*)(yr + (size_t)(r0 + 8) * CDIM + c) =
                make_float2(acc[mi][ni][2] + __low2float(x1),
                            acc[mi][ni][3] + __high2float(x1));
        }
}

// ---------------------------------------------------------------------------
// softmax(-E) over summed K-partials; writes tiled-swizzled M' = gamma*att
// ---------------------------------------------------------------------------
__global__ void __launch_bounds__(256) softmax_kernel(const float* __restrict__ gp) {
    const int i = blockIdx.x, b = blockIdx.y;
    __shared__ float sm[256];
    __shared__ __half hrow[512];
    const int t = threadIdx.x;
    float v0 = 0.0f, v1 = 0.0f;
    #pragma unroll
    for (int ks = 0; ks < KSPLIT; ks++) {
        const float* e = g_Epart + (((size_t)ks * BATCH + b) * CDIM + i) * CDIM;
        v0 += e[t];
        v1 += e[t + 256];
    }
    sm[t] = fminf(v0, v1);
    __syncthreads();
    for (int s = 128; s > 0; s >>= 1) { if (t < s) sm[t] = fminf(sm[t], sm[t + s]); __syncthreads(); }
    float mn = sm[0];
    __syncthreads();
    float w0 = __expf(mn - v0), w1 = __expf(mn - v1);
    sm[t] = w0 + w1;
    __syncthreads();
    for (int s = 128; s > 0; s >>= 1) { if (t < s) sm[t] += sm[t + s]; __syncthreads(); }
    float inv = gp[0] / sm[0];
    hrow[t]       = __float2half_rn(w0 * inv);
    hrow[t + 256] = __float2half_rn(w1 * inv);
    __syncthreads();
    if (t < 64) {
        const int s = t >> 1, h = t & 1;
        const __half* src = hrow + s * 16 + h * 8;
        uint32_t w[4];
        #pragma unroll
        for (int e = 0; e < 4; e++) w[e] = *(const uint32_t*)(src + 2 * e);
        char* blk = (char*)g_MT_h + ((size_t)(b * 4 + (i >> 7)) * 32 + s) * 4096;
        *(uint4*)(blk + swzoff(i & 127, h)) = make_uint4(w[0], w[1], w[2], w[3]);
    }
}

extern "C" void kernel_launch(void* const* d_in, const int* in_sizes, int n_in,
                              void* d_out, int out_size) {
    const float* x  = (const float*)d_in[0];
    const float* gm = (const float*)d_in[1];
    float*       y  = (float*)d_out;
    (void)in_sizes; (void)n_in; (void)out_size;

    cudaFuncSetAttribute(split_kernel,    cudaFuncAttributeMaxDynamicSharedMemorySize, SPLIT_SMEM);
    cudaFuncSetAttribute(gram_mma_kernel, cudaFuncAttributeMaxDynamicSharedMemorySize, SMEM_G);
    cudaFuncSetAttribute(out_mma_kernel,  cudaFuncAttributeMaxDynamicSharedMemorySize, SMEM_O);

    split_kernel<<<dim3(NDIM / 64, CDIM / 256, BATCH), 256, SPLIT_SMEM>>>(x);
    gram_mma_kernel<<<dim3(10, KSPLIT, BATCH), 256, SMEM_G>>>();
    softmax_kernel<<<dim3(CDIM, BATCH), 256>>>(gm);
    out_mma_kernel<<<dim3(NDIM / 128, 4, BATCH), 256, SMEM_O>>>(y);
}